// round 9
// baseline (speedup 1.0000x reference)
#include <cuda_runtime.h>
#include <cuda_bf16.h>
#include <cstdint>

#define B_ 4
#define T_ 2048
#define C_ 1024
#define H_ 16
#define D_ 64

// Pre-split bf16 hi/lo scratch (static __device__: allocation-free)
__device__ __align__(16) __nv_bfloat16 g_xH[(size_t)B_ * T_ * C_];
__device__ __align__(16) __nv_bfloat16 g_xL[(size_t)B_ * T_ * C_];
__device__ __align__(16) __nv_bfloat16 g_wqH[(size_t)C_ * 3 * C_];
__device__ __align__(16) __nv_bfloat16 g_wqL[(size_t)C_ * 3 * C_];
__device__ __align__(16) __nv_bfloat16 g_wpH[(size_t)C_ * C_];
__device__ __align__(16) __nv_bfloat16 g_wpL[(size_t)C_ * C_];
__device__ __align__(16) __nv_bfloat16 g_qkvH[(size_t)3 * B_ * H_ * T_ * D_];
__device__ __align__(16) __nv_bfloat16 g_qkvL[(size_t)3 * B_ * H_ * T_ * D_];
__device__ __align__(16) __nv_bfloat16 g_attH[(size_t)B_ * T_ * C_];
__device__ __align__(16) __nv_bfloat16 g_attL[(size_t)B_ * T_ * C_];

// ---------------------------------------------------------------------------
// Helpers (compute_103-safe: ldmatrix + mma.sync + cp.async, no tcgen05)
// ---------------------------------------------------------------------------
static __device__ __forceinline__ uint32_t smem_u32(const void* p) {
    uint32_t a;
    asm("{ .reg .u64 t; cvta.to.shared.u64 t, %1; cvt.u32.u64 %0, t; }"
        : "=r"(a) : "l"(p));
    return a;
}

#define LDM_X4(r, addr) \
    asm volatile("ldmatrix.sync.aligned.m8n8.x4.shared.b16 {%0,%1,%2,%3}, [%4];" \
        : "=r"((r)[0]), "=r"((r)[1]), "=r"((r)[2]), "=r"((r)[3]) : "r"(addr))

#define LDM_X4T(r, addr) \
    asm volatile("ldmatrix.sync.aligned.m8n8.x4.trans.shared.b16 {%0,%1,%2,%3}, [%4];" \
        : "=r"((r)[0]), "=r"((r)[1]), "=r"((r)[2]), "=r"((r)[3]) : "r"(addr))

#define MMA_BF16(d, a, b0, b1) \
    asm volatile("mma.sync.aligned.m16n8k16.row.col.f32.bf16.bf16.f32 " \
        "{%0,%1,%2,%3}, {%4,%5,%6,%7}, {%8,%9}, {%0,%1,%2,%3};" \
        : "+f"((d)[0]), "+f"((d)[1]), "+f"((d)[2]), "+f"((d)[3]) \
        : "r"((a)[0]), "r"((a)[1]), "r"((a)[2]), "r"((a)[3]), "r"(b0), "r"(b1))

#define CP16(saddr, gptr) \
    asm volatile("cp.async.cg.shared.global [%0], [%1], 16;" \
        :: "r"(saddr), "l"(gptr))
#define CP_COMMIT() asm volatile("cp.async.commit_group;")
#define CP_WAIT1()  asm volatile("cp.async.wait_group 1;")
#define CP_WAIT0()  asm volatile("cp.async.wait_group 0;")

// fp32 -> (hi, lo) bf16 split
static __device__ __forceinline__ void split2(float v, __nv_bfloat16& h, __nv_bfloat16& l) {
    h = __float2bfloat16_rn(v);
    l = __float2bfloat16_rn(v - __bfloat162float(h));
}
static __device__ __forceinline__ uint32_t pack2(__nv_bfloat16 a, __nv_bfloat16 b) {
    __nv_bfloat162 t; t.x = a; t.y = b;
    uint32_t u; __builtin_memcpy(&u, &t, 4);
    return u;
}

// ---------------------------------------------------------------------------
// Prep: elementwise fp32 -> bf16 hi/lo split. WHICH: 0=x, 1=w_qkv, 2=w_proj
// ---------------------------------------------------------------------------
template <int WHICH>
__global__ void split_kernel(const float* __restrict__ src, int n4)
{
    __nv_bfloat16* dh = (WHICH == 0) ? g_xH : (WHICH == 1) ? g_wqH : g_wpH;
    __nv_bfloat16* dl = (WHICH == 0) ? g_xL : (WHICH == 1) ? g_wqL : g_wpL;
    int i = blockIdx.x * blockDim.x + threadIdx.x;
    if (i < n4) {
        float4 v = ((const float4*)src)[i];
        __nv_bfloat16 h0, h1, h2, h3, l0, l1, l2, l3;
        split2(v.x, h0, l0); split2(v.y, h1, l1);
        split2(v.z, h2, l2); split2(v.w, h3, l3);
        ((uint2*)dh)[i] = make_uint2(pack2(h0, h1), pack2(h2, h3));
        ((uint2*)dl)[i] = make_uint2(pack2(l0, l1), pack2(l2, l3));
    }
}

// Padded strides (elements): A rows 40 bf16 (80B), B rows 136 bf16 (272B).
#define A_PITCH 40
#define B_PITCH 136

// Dynamic smem layout (bytes): double-buffered tiles
#define OFF_AH 0          // 2 x 128*80
#define OFF_AL 20480
#define OFF_WH 40960      // 2 x 32*272
#define OFF_WL 58368
#define A_BUF  10240
#define W_BUF  8704
#define SMEM_G 75776

// ---------------------------------------------------------------------------
// HMMA GEMM, bf16x3, pre-split inputs, cp.async double-buffered.
// MODE 0: A=g_x, W=g_wq, epilogue scatters split hi/lo into g_qkv.
// MODE 1: A=g_att, W=g_wp, epilogue writes fp32 out.
// BM=BN=128, BK=32, 256 threads (8 warps = 4m x 2n), warp tile 32x64.
// ---------------------------------------------------------------------------
template <int MODE>
__global__ __launch_bounds__(256) void gemm_mma(
    const float* __restrict__ bias, float* __restrict__ out,
    int M, int N, int K)
{
    extern __shared__ __align__(16) char smem[];
    const uint32_t sb = smem_u32(smem);

    const int tid = threadIdx.x;
    const int wid = tid >> 5;
    const int lane = tid & 31;
    const int wm = wid >> 1;
    const int wn = wid & 1;
    const int bm = blockIdx.y, bn = blockIdx.x;

    const __nv_bfloat16* AH = ((MODE == 0) ? g_xH : g_attH) + (size_t)bm * 128 * K;
    const __nv_bfloat16* AL = ((MODE == 0) ? g_xL : g_attL) + (size_t)bm * 128 * K;
    const __nv_bfloat16* WH = ((MODE == 0) ? g_wqH : g_wpH) + (size_t)bn * 128;
    const __nv_bfloat16* WL = ((MODE == 0) ? g_wqL : g_wpL) + (size_t)bn * 128;

    float acc[2][8][4] = {};

    const int l15 = lane & 15;
    const int lhi = lane >> 4;
    const uint32_t a_off0 = (uint32_t)(wm * 32 + l15) * (A_PITCH * 2) + (lhi << 4);
    const uint32_t b_off0 = (uint32_t)l15 * (B_PITCH * 2) + ((wn * 64 + (lhi << 3)) << 1);

    const int nt = K / 32;

    // --- tile loader: 8 x 16B cp.async per thread
    auto load_tile = [&](int kt, int bi) {
#pragma unroll
        for (int i = 0; i < 2; ++i) {        // A: 128 rows x 4 chunks (hi+lo)
            int f = tid + i * 256;
            int r = f >> 2, c = f & 3;
            const char* gh = (const char*)(AH + (size_t)r * K + kt * 32) + c * 16;
            const char* gl = (const char*)(AL + (size_t)r * K + kt * 32) + c * 16;
            CP16(sb + OFF_AH + bi * A_BUF + r * 80 + c * 16, gh);
            CP16(sb + OFF_AL + bi * A_BUF + r * 80 + c * 16, gl);
        }
#pragma unroll
        for (int i = 0; i < 2; ++i) {        // W: 32 rows x 16 chunks (hi+lo)
            int f = tid + i * 256;
            int r = f >> 4, c = f & 15;
            const char* gh = (const char*)(WH + (size_t)(kt * 32 + r) * N) + c * 16;
            const char* gl = (const char*)(WL + (size_t)(kt * 32 + r) * N) + c * 16;
            CP16(sb + OFF_WH + bi * W_BUF + r * 272 + c * 16, gh);
            CP16(sb + OFF_WL + bi * W_BUF + r * 272 + c * 16, gl);
        }
    };

    load_tile(0, 0);
    CP_COMMIT();

    for (int kt = 0; kt < nt; ++kt) {
        const int bi = kt & 1;
        if (kt + 1 < nt) {
            load_tile(kt + 1, bi ^ 1);
            CP_COMMIT();
            CP_WAIT1();
        } else {
            CP_WAIT0();
        }
        __syncthreads();

        const uint32_t sAH = sb + OFF_AH + bi * A_BUF;
        const uint32_t sAL = sb + OFF_AL + bi * A_BUF;
        const uint32_t sWH = sb + OFF_WH + bi * W_BUF;
        const uint32_t sWL = sb + OFF_WL + bi * W_BUF;

#pragma unroll
        for (int ks = 0; ks < 2; ++ks) {
            uint32_t ah[2][4], al[2][4], bfr[4][4];
#pragma unroll
            for (int mf = 0; mf < 2; ++mf) {
                uint32_t ao = a_off0 + (uint32_t)mf * 16 * (A_PITCH * 2) + ks * 32;
                LDM_X4(ah[mf], sAH + ao);
                LDM_X4(al[mf], sAL + ao);
            }
            const uint32_t bks = b_off0 + (uint32_t)ks * 16 * (B_PITCH * 2);
#pragma unroll
            for (int ng = 0; ng < 4; ++ng)
                LDM_X4T(bfr[ng], sWH + bks + ng * 32);
#pragma unroll
            for (int mf = 0; mf < 2; ++mf)
#pragma unroll
                for (int nf = 0; nf < 8; ++nf)
                    MMA_BF16(acc[mf][nf], ah[mf], bfr[nf >> 1][(nf & 1) * 2],
                             bfr[nf >> 1][(nf & 1) * 2 + 1]);
#pragma unroll
            for (int mf = 0; mf < 2; ++mf)
#pragma unroll
                for (int nf = 0; nf < 8; ++nf)
                    MMA_BF16(acc[mf][nf], al[mf], bfr[nf >> 1][(nf & 1) * 2],
                             bfr[nf >> 1][(nf & 1) * 2 + 1]);
#pragma unroll
            for (int ng = 0; ng < 4; ++ng)
                LDM_X4T(bfr[ng], sWL + bks + ng * 32);
#pragma unroll
            for (int mf = 0; mf < 2; ++mf)
#pragma unroll
                for (int nf = 0; nf < 8; ++nf)
                    MMA_BF16(acc[mf][nf], ah[mf], bfr[nf >> 1][(nf & 1) * 2],
                             bfr[nf >> 1][(nf & 1) * 2 + 1]);
        }
        __syncthreads();
    }

    // ---- epilogue
    const int tr = lane >> 2;
    const int tc = (lane & 3) * 2;
#pragma unroll
    for (int mf = 0; mf < 2; ++mf) {
        const int m0 = bm * 128 + wm * 32 + mf * 16 + tr;
#pragma unroll
        for (int nf = 0; nf < 8; ++nf) {
            const int n0 = bn * 128 + wn * 64 + nf * 8 + tc;
            const float bx = __ldg(&bias[n0]);
            const float by = __ldg(&bias[n0 + 1]);
            float2 v0 = make_float2(acc[mf][nf][0] + bx, acc[mf][nf][1] + by);
            float2 v1 = make_float2(acc[mf][nf][2] + bx, acc[mf][nf][3] + by);
            if (MODE == 0) {
                const int which = n0 >> 10;
                const int h = (n0 & 1023) >> 6;
                const int d0 = n0 & 63;
                {
                    int bb = m0 >> 11, t = m0 & 2047;
                    size_t idx = (((((size_t)which * B_ + bb) * H_ + h) * T_ + t) * D_) + d0;
                    __nv_bfloat16 h0, l0, h1, l1;
                    split2(v0.x, h0, l0); split2(v0.y, h1, l1);
                    *(uint32_t*)&g_qkvH[idx] = pack2(h0, h1);
                    *(uint32_t*)&g_qkvL[idx] = pack2(l0, l1);
                }
                {
                    int m1 = m0 + 8;
                    int bb = m1 >> 11, t = m1 & 2047;
                    size_t idx = (((((size_t)which * B_ + bb) * H_ + h) * T_ + t) * D_) + d0;
                    __nv_bfloat16 h0, l0, h1, l1;
                    split2(v1.x, h0, l0); split2(v1.y, h1, l1);
                    *(uint32_t*)&g_qkvH[idx] = pack2(h0, h1);
                    *(uint32_t*)&g_qkvL[idx] = pack2(l0, l1);
                }
            } else {
                *(float2*)(out + (size_t)m0 * N + n0) = v0;
                *(float2*)(out + (size_t)(m0 + 8) * N + n0) = v1;
            }
        }
    }
}

// ---------------------------------------------------------------------------
// HMMA flash attention, causal, bf16x3, pre-split q/k/v (no conversions).
// BQ=128 per CTA, BK=64, 256 threads = 8 warps; softmax warp-local.
// ---------------------------------------------------------------------------
#define AT_PITCH 72   // 144B rows

__global__ __launch_bounds__(256, 2) void attn_mma()
{
    __shared__ __align__(16) __nv_bfloat16 KHs[64 * AT_PITCH];
    __shared__ __align__(16) __nv_bfloat16 KLs[64 * AT_PITCH];
    __shared__ __align__(16) __nv_bfloat16 VHs[64 * AT_PITCH];
    __shared__ __align__(16) __nv_bfloat16 VLs[64 * AT_PITCH];

    const int tid = threadIdx.x;
    const int wid = tid >> 5;
    const int lane = tid & 31;
    const int l15 = lane & 15;
    const int lhi = lane >> 4;
    const int tr = lane >> 2;
    const int tc = (lane & 3) * 2;

    const int qb = blockIdx.x;
    const int bh = blockIdx.y;
    const int q0 = qb * 128;

    const uint32_t sKH = smem_u32(KHs), sKL = smem_u32(KLs);
    const uint32_t sVH = smem_u32(VHs), sVL = smem_u32(VLs);

    const size_t plane = (size_t)B_ * H_ * T_ * D_;
    const __nv_bfloat16* qHb = g_qkvH + ((size_t)bh * T_ + q0) * D_;
    const __nv_bfloat16* qLb = g_qkvL + ((size_t)bh * T_ + q0) * D_;
    const __nv_bfloat16* kHb = g_qkvH + plane + (size_t)bh * T_ * D_;
    const __nv_bfloat16* kLb = g_qkvL + plane + (size_t)bh * T_ * D_;
    const __nv_bfloat16* vHb = kHb + plane;
    const __nv_bfloat16* vLb = kLb + plane;

    // ---- Q tile -> registers (hi/lo A-frags), staged through KH/KL in halves
    uint32_t qh[4][4], ql[4][4];
#pragma unroll
    for (int half = 0; half < 2; ++half) {
        const uint4* qh4 = (const uint4*)(qHb + (size_t)half * 64 * D_);
        const uint4* ql4 = (const uint4*)(qLb + (size_t)half * 64 * D_);
#pragma unroll
        for (int i = 0; i < 2; ++i) {
            int f = tid + i * 256;
            int r = f >> 3, c = f & 7;
            int e = r * AT_PITCH + c * 8;
            *(uint4*)&KHs[e] = qh4[f];
            *(uint4*)&KLs[e] = ql4[f];
        }
        __syncthreads();
        if ((wid >> 2) == half) {
            const uint32_t qoff =
                (uint32_t)((wid & 3) * 16 + l15) * (AT_PITCH * 2) + (lhi << 4);
#pragma unroll
            for (int s = 0; s < 4; ++s) {
                LDM_X4(qh[s], sKH + qoff + s * 32);
                LDM_X4(ql[s], sKL + qoff + s * 32);
            }
        }
        __syncthreads();
    }

    float o[8][4] = {};
    float m0 = -1e30f, m1 = -1e30f, lsum0 = 0.f, lsum1 = 0.f;

    const int row0 = q0 + wid * 16 + tr;
    const int row1 = row0 + 8;
    const int warp_qhi = q0 + wid * 16 + 15;
    const int ktiles = 2 * qb + 2;

    for (int kb = 0; kb < ktiles; ++kb) {
        __syncthreads();
        const uint4* kh4 = (const uint4*)(kHb + (size_t)kb * 64 * D_);
        const uint4* kl4 = (const uint4*)(kLb + (size_t)kb * 64 * D_);
        const uint4* vh4g = (const uint4*)(vHb + (size_t)kb * 64 * D_);
        const uint4* vl4g = (const uint4*)(vLb + (size_t)kb * 64 * D_);
#pragma unroll
        for (int i = 0; i < 2; ++i) {
            int f = tid + i * 256;
            int r = f >> 3, c = f & 7;
            int e = r * AT_PITCH + c * 8;
            *(uint4*)&KHs[e] = kh4[f];
            *(uint4*)&KLs[e] = kl4[f];
            *(uint4*)&VHs[e] = vh4g[f];
            *(uint4*)&VLs[e] = vl4g[f];
        }
        __syncthreads();

        if (kb * 64 > warp_qhi) continue;

        // ---- S = Q @ K^T (bf16x3)
        float s[8][4] = {};
#pragma unroll
        for (int ks = 0; ks < 4; ++ks)
#pragma unroll
            for (int ng = 0; ng < 4; ++ng) {
                uint32_t bh4[4], bl4[4];
                const uint32_t ka =
                    (uint32_t)(ng * 16 + l15) * (AT_PITCH * 2) + ks * 32 + (lhi << 4);
                LDM_X4(bh4, sKH + ka);
                LDM_X4(bl4, sKL + ka);
                MMA_BF16(s[2 * ng],     qh[ks], bh4[0], bh4[2]);
                MMA_BF16(s[2 * ng + 1], qh[ks], bh4[1], bh4[3]);
                MMA_BF16(s[2 * ng],     qh[ks], bl4[0], bl4[2]);
                MMA_BF16(s[2 * ng + 1], qh[ks], bl4[1], bl4[3]);
                MMA_BF16(s[2 * ng],     ql[ks], bh4[0], bh4[2]);
                MMA_BF16(s[2 * ng + 1], ql[ks], bh4[1], bh4[3]);
            }

        // ---- scale + causal mask
        const bool diag = (kb >= 2 * qb);
#pragma unroll
        for (int nf = 0; nf < 8; ++nf) {
            const int c0 = kb * 64 + nf * 8 + tc;
            s[nf][0] *= 0.125f; s[nf][1] *= 0.125f;
            s[nf][2] *= 0.125f; s[nf][3] *= 0.125f;
            if (diag) {
                if (c0 > row0)     s[nf][0] = -1e30f;
                if (c0 + 1 > row0) s[nf][1] = -1e30f;
                if (c0 > row1)     s[nf][2] = -1e30f;
                if (c0 + 1 > row1) s[nf][3] = -1e30f;
            }
        }

        // ---- online softmax
        float mt0 = -1e30f, mt1 = -1e30f;
#pragma unroll
        for (int nf = 0; nf < 8; ++nf) {
            mt0 = fmaxf(mt0, fmaxf(s[nf][0], s[nf][1]));
            mt1 = fmaxf(mt1, fmaxf(s[nf][2], s[nf][3]));
        }
        mt0 = fmaxf(mt0, __shfl_xor_sync(0xffffffffu, mt0, 1));
        mt0 = fmaxf(mt0, __shfl_xor_sync(0xffffffffu, mt0, 2));
        mt1 = fmaxf(mt1, __shfl_xor_sync(0xffffffffu, mt1, 1));
        mt1 = fmaxf(mt1, __shfl_xor_sync(0xffffffffu, mt1, 2));
        const float mn0 = fmaxf(m0, mt0), mn1 = fmaxf(m1, mt1);
        const float al0 = __expf(m0 - mn0), al1 = __expf(m1 - mn1);
        m0 = mn0; m1 = mn1;

        float rs0 = 0.f, rs1 = 0.f;
#pragma unroll
        for (int nf = 0; nf < 8; ++nf) {
            s[nf][0] = __expf(s[nf][0] - mn0);
            s[nf][1] = __expf(s[nf][1] - mn0);
            s[nf][2] = __expf(s[nf][2] - mn1);
            s[nf][3] = __expf(s[nf][3] - mn1);
            rs0 += s[nf][0] + s[nf][1];
            rs1 += s[nf][2] + s[nf][3];
        }
        rs0 += __shfl_xor_sync(0xffffffffu, rs0, 1);
        rs0 += __shfl_xor_sync(0xffffffffu, rs0, 2);
        rs1 += __shfl_xor_sync(0xffffffffu, rs1, 1);
        rs1 += __shfl_xor_sync(0xffffffffu, rs1, 2);
        lsum0 = lsum0 * al0 + rs0;
        lsum1 = lsum1 * al1 + rs1;
#pragma unroll
        for (int nf = 0; nf < 8; ++nf) {
            o[nf][0] *= al0; o[nf][1] *= al0;
            o[nf][2] *= al1; o[nf][3] *= al1;
        }

        // ---- O += P @ V (bf16x3; P frags rebuilt in registers)
#pragma unroll
        for (int ks = 0; ks < 4; ++ks) {
            uint32_t ah[4], alo[4];
            {
                const float* p0 = s[2 * ks];
                const float* p1 = s[2 * ks + 1];
                float hv[8], lv[8];
                const float pv[8] = {p0[0], p0[1], p0[2], p0[3],
                                     p1[0], p1[1], p1[2], p1[3]};
#pragma unroll
                for (int e = 0; e < 8; ++e) {
                    __nv_bfloat16 hh, ll;
                    split2(pv[e], hh, ll);
                    hv[e] = __bfloat162float(hh);
                    lv[e] = pv[e] - hv[e];
                }
                ah[0] = pack2(__float2bfloat16_rn(hv[0]), __float2bfloat16_rn(hv[1]));
                ah[1] = pack2(__float2bfloat16_rn(hv[2]), __float2bfloat16_rn(hv[3]));
                ah[2] = pack2(__float2bfloat16_rn(hv[4]), __float2bfloat16_rn(hv[5]));
                ah[3] = pack2(__float2bfloat16_rn(hv[6]), __float2bfloat16_rn(hv[7]));
                alo[0] = pack2(__float2bfloat16_rn(lv[0]), __float2bfloat16_rn(lv[1]));
                alo[1] = pack2(__float2bfloat16_rn(lv[2]), __float2bfloat16_rn(lv[3]));
                alo[2] = pack2(__float2bfloat16_rn(lv[4]), __float2bfloat16_rn(lv[5]));
                alo[3] = pack2(__float2bfloat16_rn(lv[6]), __float2bfloat16_rn(lv[7]));
            }
#pragma unroll
            for (int ng = 0; ng < 4; ++ng) {
                uint32_t vh4[4], vl4[4];
                const uint32_t va =
                    (uint32_t)(ks * 16 + l15) * (AT_PITCH * 2) + ((ng * 16 + lhi * 8) << 1);
                LDM_X4T(vh4, sVH + va);
                LDM_X4T(vl4, sVL + va);
                MMA_BF16(o[2 * ng],     ah,  vh4[0], vh4[1]);
                MMA_BF16(o[2 * ng + 1], ah,  vh4[2], vh4[3]);
                MMA_BF16(o[2 * ng],     ah,  vl4[0], vl4[1]);
                MMA_BF16(o[2 * ng + 1], ah,  vl4[2], vl4[3]);
                MMA_BF16(o[2 * ng],     alo, vh4[0], vh4[1]);
                MMA_BF16(o[2 * ng + 1], alo, vh4[2], vh4[3]);
            }
        }
    }

    // ---- normalize + write pre-split to g_att [B, T, H*D]
    const int b = bh >> 4, h = bh & 15;
    const float inv0 = 1.0f / lsum0;
    const float inv1 = 1.0f / lsum1;
    const size_t i0 = (size_t)(b * T_ + row0) * C_ + h * D_;
    const size_t i1 = (size_t)(b * T_ + row1) * C_ + h * D_;
#pragma unroll
    for (int nf = 0; nf < 8; ++nf) {
        const int d = nf * 8 + tc;
        __nv_bfloat16 h0, l0, h1, l1;
        split2(o[nf][0] * inv0, h0, l0); split2(o[nf][1] * inv0, h1, l1);
        *(uint32_t*)&g_attH[i0 + d] = pack2(h0, h1);
        *(uint32_t*)&g_attL[i0 + d] = pack2(l0, l1);
        split2(o[nf][2] * inv1, h0, l0); split2(o[nf][3] * inv1, h1, l1);
        *(uint32_t*)&g_attH[i1 + d] = pack2(h0, h1);
        *(uint32_t*)&g_attL[i1 + d] = pack2(l0, l1);
    }
}

// ---------------------------------------------------------------------------
extern "C" void kernel_launch(void* const* d_in, const int* in_sizes, int n_in,
                              void* d_out, int out_size)
{
    const float* x      = (const float*)d_in[0];
    const float* w_qkv  = (const float*)d_in[1];
    const float* b_qkv  = (const float*)d_in[2];
    const float* w_proj = (const float*)d_in[3];
    const float* b_proj = (const float*)d_in[4];
    float* out = (float*)d_out;

    cudaFuncSetAttribute(gemm_mma<0>, cudaFuncAttributeMaxDynamicSharedMemorySize, SMEM_G);
    cudaFuncSetAttribute(gemm_mma<1>, cudaFuncAttributeMaxDynamicSharedMemorySize, SMEM_G);

    // 0) pre-split inputs to bf16 hi/lo
    {
        int n4x = (B_ * T_ * C_) / 4;
        int n4q = (C_ * 3 * C_) / 4;
        int n4p = (C_ * C_) / 4;
        split_kernel<0><<<(n4x + 255) / 256, 256>>>(x, n4x);
        split_kernel<1><<<(n4q + 255) / 256, 256>>>(w_qkv, n4q);
        split_kernel<2><<<(n4p + 255) / 256, 256>>>(w_proj, n4p);
    }

    // 1) QKV projection (HMMA bf16x3, cp.async pipelined)
    gemm_mma<0><<<dim3((3 * C_) / 128, (B_ * T_) / 128), 256, SMEM_G>>>(
        b_qkv, nullptr, B_ * T_, 3 * C_, C_);

    // 2) causal flash attention (HMMA bf16x3) -> g_att hi/lo
    attn_mma<<<dim3(T_ / 128, B_ * H_), 256>>>();

    // 3) output projection (HMMA bf16x3, cp.async pipelined)
    gemm_mma<1><<<dim3(C_ / 128, (B_ * T_) / 128), 256, SMEM_G>>>(
        b_proj, out, B_ * T_, C_, C_);
}

// round 10
// speedup vs baseline: 1.0824x; 1.0824x over previous
#include <cuda_runtime.h>
#include <cuda_bf16.h>
#include <cstdint>

#define B_ 4
#define T_ 2048
#define C_ 1024
#define H_ 16
#define D_ 64

// Pre-split bf16 hi/lo scratch (static __device__: allocation-free)
__device__ __align__(16) __nv_bfloat16 g_xH[(size_t)B_ * T_ * C_];
__device__ __align__(16) __nv_bfloat16 g_xL[(size_t)B_ * T_ * C_];
__device__ __align__(16) __nv_bfloat16 g_wqH[(size_t)C_ * 3 * C_];
__device__ __align__(16) __nv_bfloat16 g_wqL[(size_t)C_ * 3 * C_];
__device__ __align__(16) __nv_bfloat16 g_wpH[(size_t)C_ * C_];
__device__ __align__(16) __nv_bfloat16 g_wpL[(size_t)C_ * C_];
__device__ __align__(16) __nv_bfloat16 g_qkvH[(size_t)3 * B_ * H_ * T_ * D_];
__device__ __align__(16) __nv_bfloat16 g_qkvL[(size_t)3 * B_ * H_ * T_ * D_];
__device__ __align__(16) __nv_bfloat16 g_attH[(size_t)B_ * T_ * C_];
__device__ __align__(16) __nv_bfloat16 g_attL[(size_t)B_ * T_ * C_];

// ---------------------------------------------------------------------------
// Helpers (compute_103-safe: ldmatrix + mma.sync + cp.async, no tcgen05)
// ---------------------------------------------------------------------------
static __device__ __forceinline__ uint32_t smem_u32(const void* p) {
    uint32_t a;
    asm("{ .reg .u64 t; cvta.to.shared.u64 t, %1; cvt.u32.u64 %0, t; }"
        : "=r"(a) : "l"(p));
    return a;
}

#define LDM_X4(r, addr) \
    asm volatile("ldmatrix.sync.aligned.m8n8.x4.shared.b16 {%0,%1,%2,%3}, [%4];" \
        : "=r"((r)[0]), "=r"((r)[1]), "=r"((r)[2]), "=r"((r)[3]) : "r"(addr))

#define LDM_X4T(r, addr) \
    asm volatile("ldmatrix.sync.aligned.m8n8.x4.trans.shared.b16 {%0,%1,%2,%3}, [%4];" \
        : "=r"((r)[0]), "=r"((r)[1]), "=r"((r)[2]), "=r"((r)[3]) : "r"(addr))

#define MMA_BF16(d, a, b0, b1) \
    asm volatile("mma.sync.aligned.m16n8k16.row.col.f32.bf16.bf16.f32 " \
        "{%0,%1,%2,%3}, {%4,%5,%6,%7}, {%8,%9}, {%0,%1,%2,%3};" \
        : "+f"((d)[0]), "+f"((d)[1]), "+f"((d)[2]), "+f"((d)[3]) \
        : "r"((a)[0]), "r"((a)[1]), "r"((a)[2]), "r"((a)[3]), "r"(b0), "r"(b1))

#define CP16(saddr, gptr) \
    asm volatile("cp.async.cg.shared.global [%0], [%1], 16;" \
        :: "r"(saddr), "l"(gptr))
#define CP_COMMIT() asm volatile("cp.async.commit_group;")
#define CP_WAIT1()  asm volatile("cp.async.wait_group 1;")
#define CP_WAIT0()  asm volatile("cp.async.wait_group 0;")

// fp32 -> (hi, lo) bf16 split
static __device__ __forceinline__ void split2(float v, __nv_bfloat16& h, __nv_bfloat16& l) {
    h = __float2bfloat16_rn(v);
    l = __float2bfloat16_rn(v - __bfloat162float(h));
}
static __device__ __forceinline__ uint32_t pack2(__nv_bfloat16 a, __nv_bfloat16 b) {
    __nv_bfloat162 t; t.x = a; t.y = b;
    uint32_t u; __builtin_memcpy(&u, &t, 4);
    return u;
}

// ---------------------------------------------------------------------------
// Prep: elementwise fp32 -> bf16 hi/lo split. WHICH: 0=x, 1=w_qkv, 2=w_proj
// ---------------------------------------------------------------------------
template <int WHICH>
__global__ void split_kernel(const float* __restrict__ src, int n4)
{
    __nv_bfloat16* dh = (WHICH == 0) ? g_xH : (WHICH == 1) ? g_wqH : g_wpH;
    __nv_bfloat16* dl = (WHICH == 0) ? g_xL : (WHICH == 1) ? g_wqL : g_wpL;
    int i = blockIdx.x * blockDim.x + threadIdx.x;
    if (i < n4) {
        float4 v = ((const float4*)src)[i];
        __nv_bfloat16 h0, h1, h2, h3, l0, l1, l2, l3;
        split2(v.x, h0, l0); split2(v.y, h1, l1);
        split2(v.z, h2, l2); split2(v.w, h3, l3);
        ((uint2*)dh)[i] = make_uint2(pack2(h0, h1), pack2(h2, h3));
        ((uint2*)dl)[i] = make_uint2(pack2(l0, l1), pack2(l2, l3));
    }
}

// Padded strides (elements): A rows 40 bf16 (80B), B rows 136 bf16 (272B).
#define A_PITCH 40
#define B_PITCH 136

// Dynamic smem layout (bytes): double-buffered tiles
#define OFF_AH 0          // 2 x 128*80
#define OFF_AL 20480
#define OFF_WH 40960      // 2 x 32*272
#define OFF_WL 58368
#define A_BUF  10240
#define W_BUF  8704
#define SMEM_G 75776

// ---------------------------------------------------------------------------
// HMMA GEMM, bf16x3, pre-split inputs, cp.async double-buffered.
// MODE 0: A=g_x, W=g_wq, epilogue scatters split hi/lo into g_qkv.
// MODE 1: A=g_att, W=g_wp, epilogue writes fp32 out.
// BM=BN=128, BK=32, 256 threads (8 warps = 4m x 2n), warp tile 32x64.
// __launch_bounds__(256,2) is load-bearing: caps regs at 128 so TWO CTAs fit
// the 64K register file (round-9 regression: 134 regs -> 1 CTA/SM).
// ---------------------------------------------------------------------------
template <int MODE>
__global__ __launch_bounds__(256, 2) void gemm_mma(
    const float* __restrict__ bias, float* __restrict__ out,
    int M, int N, int K)
{
    extern __shared__ __align__(16) char smem[];
    const uint32_t sb = smem_u32(smem);

    const int tid = threadIdx.x;
    const int wid = tid >> 5;
    const int lane = tid & 31;
    const int wm = wid >> 1;
    const int wn = wid & 1;
    const int bm = blockIdx.y, bn = blockIdx.x;

    const __nv_bfloat16* AH = ((MODE == 0) ? g_xH : g_attH) + (size_t)bm * 128 * K;
    const __nv_bfloat16* AL = ((MODE == 0) ? g_xL : g_attL) + (size_t)bm * 128 * K;
    const __nv_bfloat16* WH = ((MODE == 0) ? g_wqH : g_wpH) + (size_t)bn * 128;
    const __nv_bfloat16* WL = ((MODE == 0) ? g_wqL : g_wpL) + (size_t)bn * 128;

    float acc[2][8][4] = {};

    const int l15 = lane & 15;
    const int lhi = lane >> 4;
    const uint32_t a_off0 = (uint32_t)(wm * 32 + l15) * (A_PITCH * 2) + (lhi << 4);
    const uint32_t b_off0 = (uint32_t)l15 * (B_PITCH * 2) + ((wn * 64 + (lhi << 3)) << 1);

    const int nt = K / 32;

    // --- tile loader: 8 x 16B cp.async per thread
    auto load_tile = [&](int kt, int bi) {
#pragma unroll
        for (int i = 0; i < 2; ++i) {        // A: 128 rows x 4 chunks (hi+lo)
            int f = tid + i * 256;
            int r = f >> 2, c = f & 3;
            const char* gh = (const char*)(AH + (size_t)r * K + kt * 32) + c * 16;
            const char* gl = (const char*)(AL + (size_t)r * K + kt * 32) + c * 16;
            CP16(sb + OFF_AH + bi * A_BUF + r * 80 + c * 16, gh);
            CP16(sb + OFF_AL + bi * A_BUF + r * 80 + c * 16, gl);
        }
#pragma unroll
        for (int i = 0; i < 2; ++i) {        // W: 32 rows x 16 chunks (hi+lo)
            int f = tid + i * 256;
            int r = f >> 4, c = f & 15;
            const char* gh = (const char*)(WH + (size_t)(kt * 32 + r) * N) + c * 16;
            const char* gl = (const char*)(WL + (size_t)(kt * 32 + r) * N) + c * 16;
            CP16(sb + OFF_WH + bi * W_BUF + r * 272 + c * 16, gh);
            CP16(sb + OFF_WL + bi * W_BUF + r * 272 + c * 16, gl);
        }
    };

    load_tile(0, 0);
    CP_COMMIT();

    for (int kt = 0; kt < nt; ++kt) {
        const int bi = kt & 1;
        if (kt + 1 < nt) {
            load_tile(kt + 1, bi ^ 1);
            CP_COMMIT();
            CP_WAIT1();
        } else {
            CP_WAIT0();
        }
        __syncthreads();

        const uint32_t sAH = sb + OFF_AH + bi * A_BUF;
        const uint32_t sAL = sb + OFF_AL + bi * A_BUF;
        const uint32_t sWH = sb + OFF_WH + bi * W_BUF;
        const uint32_t sWL = sb + OFF_WL + bi * W_BUF;

#pragma unroll
        for (int ks = 0; ks < 2; ++ks) {
            uint32_t ah[2][4], al[2][4], bfr[4][4];
#pragma unroll
            for (int mf = 0; mf < 2; ++mf) {
                uint32_t ao = a_off0 + (uint32_t)mf * 16 * (A_PITCH * 2) + ks * 32;
                LDM_X4(ah[mf], sAH + ao);
                LDM_X4(al[mf], sAL + ao);
            }
            const uint32_t bks = b_off0 + (uint32_t)ks * 16 * (B_PITCH * 2);
#pragma unroll
            for (int ng = 0; ng < 4; ++ng)
                LDM_X4T(bfr[ng], sWH + bks + ng * 32);
#pragma unroll
            for (int mf = 0; mf < 2; ++mf)
#pragma unroll
                for (int nf = 0; nf < 8; ++nf)
                    MMA_BF16(acc[mf][nf], ah[mf], bfr[nf >> 1][(nf & 1) * 2],
                             bfr[nf >> 1][(nf & 1) * 2 + 1]);
#pragma unroll
            for (int mf = 0; mf < 2; ++mf)
#pragma unroll
                for (int nf = 0; nf < 8; ++nf)
                    MMA_BF16(acc[mf][nf], al[mf], bfr[nf >> 1][(nf & 1) * 2],
                             bfr[nf >> 1][(nf & 1) * 2 + 1]);
#pragma unroll
            for (int ng = 0; ng < 4; ++ng)
                LDM_X4T(bfr[ng], sWL + bks + ng * 32);
#pragma unroll
            for (int mf = 0; mf < 2; ++mf)
#pragma unroll
                for (int nf = 0; nf < 8; ++nf)
                    MMA_BF16(acc[mf][nf], ah[mf], bfr[nf >> 1][(nf & 1) * 2],
                             bfr[nf >> 1][(nf & 1) * 2 + 1]);
        }
        __syncthreads();
    }

    // ---- epilogue
    const int tr = lane >> 2;
    const int tc = (lane & 3) * 2;
#pragma unroll
    for (int mf = 0; mf < 2; ++mf) {
        const int m0 = bm * 128 + wm * 32 + mf * 16 + tr;
#pragma unroll
        for (int nf = 0; nf < 8; ++nf) {
            const int n0 = bn * 128 + wn * 64 + nf * 8 + tc;
            const float bx = __ldg(&bias[n0]);
            const float by = __ldg(&bias[n0 + 1]);
            float2 v0 = make_float2(acc[mf][nf][0] + bx, acc[mf][nf][1] + by);
            float2 v1 = make_float2(acc[mf][nf][2] + bx, acc[mf][nf][3] + by);
            if (MODE == 0) {
                const int which = n0 >> 10;
                const int h = (n0 & 1023) >> 6;
                const int d0 = n0 & 63;
                {
                    int bb = m0 >> 11, t = m0 & 2047;
                    size_t idx = (((((size_t)which * B_ + bb) * H_ + h) * T_ + t) * D_) + d0;
                    __nv_bfloat16 h0, l0, h1, l1;
                    split2(v0.x, h0, l0); split2(v0.y, h1, l1);
                    *(uint32_t*)&g_qkvH[idx] = pack2(h0, h1);
                    *(uint32_t*)&g_qkvL[idx] = pack2(l0, l1);
                }
                {
                    int m1 = m0 + 8;
                    int bb = m1 >> 11, t = m1 & 2047;
                    size_t idx = (((((size_t)which * B_ + bb) * H_ + h) * T_ + t) * D_) + d0;
                    __nv_bfloat16 h0, l0, h1, l1;
                    split2(v1.x, h0, l0); split2(v1.y, h1, l1);
                    *(uint32_t*)&g_qkvH[idx] = pack2(h0, h1);
                    *(uint32_t*)&g_qkvL[idx] = pack2(l0, l1);
                }
            } else {
                *(float2*)(out + (size_t)m0 * N + n0) = v0;
                *(float2*)(out + (size_t)(m0 + 8) * N + n0) = v1;
            }
        }
    }
}

// ---------------------------------------------------------------------------
// HMMA flash attention, causal, bf16x3, pre-split q/k/v (no conversions).
// BQ=128 per CTA, BK=64, 256 threads = 8 warps; softmax warp-local.
// ---------------------------------------------------------------------------
#define AT_PITCH 72   // 144B rows

__global__ __launch_bounds__(256, 2) void attn_mma()
{
    __shared__ __align__(16) __nv_bfloat16 KHs[64 * AT_PITCH];
    __shared__ __align__(16) __nv_bfloat16 KLs[64 * AT_PITCH];
    __shared__ __align__(16) __nv_bfloat16 VHs[64 * AT_PITCH];
    __shared__ __align__(16) __nv_bfloat16 VLs[64 * AT_PITCH];

    const int tid = threadIdx.x;
    const int wid = tid >> 5;
    const int lane = tid & 31;
    const int l15 = lane & 15;
    const int lhi = lane >> 4;
    const int tr = lane >> 2;
    const int tc = (lane & 3) * 2;

    const int qb = blockIdx.x;
    const int bh = blockIdx.y;
    const int q0 = qb * 128;

    const uint32_t sKH = smem_u32(KHs), sKL = smem_u32(KLs);
    const uint32_t sVH = smem_u32(VHs), sVL = smem_u32(VLs);

    const size_t plane = (size_t)B_ * H_ * T_ * D_;
    const __nv_bfloat16* qHb = g_qkvH + ((size_t)bh * T_ + q0) * D_;
    const __nv_bfloat16* qLb = g_qkvL + ((size_t)bh * T_ + q0) * D_;
    const __nv_bfloat16* kHb = g_qkvH + plane + (size_t)bh * T_ * D_;
    const __nv_bfloat16* kLb = g_qkvL + plane + (size_t)bh * T_ * D_;
    const __nv_bfloat16* vHb = kHb + plane;
    const __nv_bfloat16* vLb = kLb + plane;

    // ---- Q tile -> registers (hi/lo A-frags), staged through KH/KL in halves
    uint32_t qh[4][4], ql[4][4];
#pragma unroll
    for (int half = 0; half < 2; ++half) {
        const uint4* qh4 = (const uint4*)(qHb + (size_t)half * 64 * D_);
        const uint4* ql4 = (const uint4*)(qLb + (size_t)half * 64 * D_);
#pragma unroll
        for (int i = 0; i < 2; ++i) {
            int f = tid + i * 256;
            int r = f >> 3, c = f & 7;
            int e = r * AT_PITCH + c * 8;
            *(uint4*)&KHs[e] = qh4[f];
            *(uint4*)&KLs[e] = ql4[f];
        }
        __syncthreads();
        if ((wid >> 2) == half) {
            const uint32_t qoff =
                (uint32_t)((wid & 3) * 16 + l15) * (AT_PITCH * 2) + (lhi << 4);
#pragma unroll
            for (int s = 0; s < 4; ++s) {
                LDM_X4(qh[s], sKH + qoff + s * 32);
                LDM_X4(ql[s], sKL + qoff + s * 32);
            }
        }
        __syncthreads();
    }

    float o[8][4] = {};
    float m0 = -1e30f, m1 = -1e30f, lsum0 = 0.f, lsum1 = 0.f;

    const int row0 = q0 + wid * 16 + tr;
    const int row1 = row0 + 8;
    const int warp_qhi = q0 + wid * 16 + 15;
    const int ktiles = 2 * qb + 2;

    for (int kb = 0; kb < ktiles; ++kb) {
        __syncthreads();
        const uint4* kh4 = (const uint4*)(kHb + (size_t)kb * 64 * D_);
        const uint4* kl4 = (const uint4*)(kLb + (size_t)kb * 64 * D_);
        const uint4* vh4g = (const uint4*)(vHb + (size_t)kb * 64 * D_);
        const uint4* vl4g = (const uint4*)(vLb + (size_t)kb * 64 * D_);
#pragma unroll
        for (int i = 0; i < 2; ++i) {
            int f = tid + i * 256;
            int r = f >> 3, c = f & 7;
            int e = r * AT_PITCH + c * 8;
            *(uint4*)&KHs[e] = kh4[f];
            *(uint4*)&KLs[e] = kl4[f];
            *(uint4*)&VHs[e] = vh4g[f];
            *(uint4*)&VLs[e] = vl4g[f];
        }
        __syncthreads();

        if (kb * 64 > warp_qhi) continue;

        // ---- S = Q @ K^T (bf16x3)
        float s[8][4] = {};
#pragma unroll
        for (int ks = 0; ks < 4; ++ks)
#pragma unroll
            for (int ng = 0; ng < 4; ++ng) {
                uint32_t bh4[4], bl4[4];
                const uint32_t ka =
                    (uint32_t)(ng * 16 + l15) * (AT_PITCH * 2) + ks * 32 + (lhi << 4);
                LDM_X4(bh4, sKH + ka);
                LDM_X4(bl4, sKL + ka);
                MMA_BF16(s[2 * ng],     qh[ks], bh4[0], bh4[2]);
                MMA_BF16(s[2 * ng + 1], qh[ks], bh4[1], bh4[3]);
                MMA_BF16(s[2 * ng],     qh[ks], bl4[0], bl4[2]);
                MMA_BF16(s[2 * ng + 1], qh[ks], bl4[1], bl4[3]);
                MMA_BF16(s[2 * ng],     ql[ks], bh4[0], bh4[2]);
                MMA_BF16(s[2 * ng + 1], ql[ks], bh4[1], bh4[3]);
            }

        // ---- scale + causal mask
        const bool diag = (kb >= 2 * qb);
#pragma unroll
        for (int nf = 0; nf < 8; ++nf) {
            const int c0 = kb * 64 + nf * 8 + tc;
            s[nf][0] *= 0.125f; s[nf][1] *= 0.125f;
            s[nf][2] *= 0.125f; s[nf][3] *= 0.125f;
            if (diag) {
                if (c0 > row0)     s[nf][0] = -1e30f;
                if (c0 + 1 > row0) s[nf][1] = -1e30f;
                if (c0 > row1)     s[nf][2] = -1e30f;
                if (c0 + 1 > row1) s[nf][3] = -1e30f;
            }
        }

        // ---- online softmax
        float mt0 = -1e30f, mt1 = -1e30f;
#pragma unroll
        for (int nf = 0; nf < 8; ++nf) {
            mt0 = fmaxf(mt0, fmaxf(s[nf][0], s[nf][1]));
            mt1 = fmaxf(mt1, fmaxf(s[nf][2], s[nf][3]));
        }
        mt0 = fmaxf(mt0, __shfl_xor_sync(0xffffffffu, mt0, 1));
        mt0 = fmaxf(mt0, __shfl_xor_sync(0xffffffffu, mt0, 2));
        mt1 = fmaxf(mt1, __shfl_xor_sync(0xffffffffu, mt1, 1));
        mt1 = fmaxf(mt1, __shfl_xor_sync(0xffffffffu, mt1, 2));
        const float mn0 = fmaxf(m0, mt0), mn1 = fmaxf(m1, mt1);
        const float al0 = __expf(m0 - mn0), al1 = __expf(m1 - mn1);
        m0 = mn0; m1 = mn1;

        float rs0 = 0.f, rs1 = 0.f;
#pragma unroll
        for (int nf = 0; nf < 8; ++nf) {
            s[nf][0] = __expf(s[nf][0] - mn0);
            s[nf][1] = __expf(s[nf][1] - mn0);
            s[nf][2] = __expf(s[nf][2] - mn1);
            s[nf][3] = __expf(s[nf][3] - mn1);
            rs0 += s[nf][0] + s[nf][1];
            rs1 += s[nf][2] + s[nf][3];
        }
        rs0 += __shfl_xor_sync(0xffffffffu, rs0, 1);
        rs0 += __shfl_xor_sync(0xffffffffu, rs0, 2);
        rs1 += __shfl_xor_sync(0xffffffffu, rs1, 1);
        rs1 += __shfl_xor_sync(0xffffffffu, rs1, 2);
        lsum0 = lsum0 * al0 + rs0;
        lsum1 = lsum1 * al1 + rs1;
#pragma unroll
        for (int nf = 0; nf < 8; ++nf) {
            o[nf][0] *= al0; o[nf][1] *= al0;
            o[nf][2] *= al1; o[nf][3] *= al1;
        }

        // ---- O += P @ V (bf16x3; P frags rebuilt in registers)
#pragma unroll
        for (int ks = 0; ks < 4; ++ks) {
            uint32_t ah[4], alo[4];
            {
                const float* p0 = s[2 * ks];
                const float* p1 = s[2 * ks + 1];
                float hv[8], lv[8];
                const float pv[8] = {p0[0], p0[1], p0[2], p0[3],
                                     p1[0], p1[1], p1[2], p1[3]};
#pragma unroll
                for (int e = 0; e < 8; ++e) {
                    __nv_bfloat16 hh, ll;
                    split2(pv[e], hh, ll);
                    hv[e] = __bfloat162float(hh);
                    lv[e] = pv[e] - hv[e];
                }
                ah[0] = pack2(__float2bfloat16_rn(hv[0]), __float2bfloat16_rn(hv[1]));
                ah[1] = pack2(__float2bfloat16_rn(hv[2]), __float2bfloat16_rn(hv[3]));
                ah[2] = pack2(__float2bfloat16_rn(hv[4]), __float2bfloat16_rn(hv[5]));
                ah[3] = pack2(__float2bfloat16_rn(hv[6]), __float2bfloat16_rn(hv[7]));
                alo[0] = pack2(__float2bfloat16_rn(lv[0]), __float2bfloat16_rn(lv[1]));
                alo[1] = pack2(__float2bfloat16_rn(lv[2]), __float2bfloat16_rn(lv[3]));
                alo[2] = pack2(__float2bfloat16_rn(lv[4]), __float2bfloat16_rn(lv[5]));
                alo[3] = pack2(__float2bfloat16_rn(lv[6]), __float2bfloat16_rn(lv[7]));
            }
#pragma unroll
            for (int ng = 0; ng < 4; ++ng) {
                uint32_t vh4[4], vl4[4];
                const uint32_t va =
                    (uint32_t)(ks * 16 + l15) * (AT_PITCH * 2) + ((ng * 16 + lhi * 8) << 1);
                LDM_X4T(vh4, sVH + va);
                LDM_X4T(vl4, sVL + va);
                MMA_BF16(o[2 * ng],     ah,  vh4[0], vh4[1]);
                MMA_BF16(o[2 * ng + 1], ah,  vh4[2], vh4[3]);
                MMA_BF16(o[2 * ng],     ah,  vl4[0], vl4[1]);
                MMA_BF16(o[2 * ng + 1], ah,  vl4[2], vl4[3]);
                MMA_BF16(o[2 * ng],     alo, vh4[0], vh4[1]);
                MMA_BF16(o[2 * ng + 1], alo, vh4[2], vh4[3]);
            }
        }
    }

    // ---- normalize + write pre-split to g_att [B, T, H*D]
    const int b = bh >> 4, h = bh & 15;
    const float inv0 = 1.0f / lsum0;
    const float inv1 = 1.0f / lsum1;
    const size_t i0 = (size_t)(b * T_ + row0) * C_ + h * D_;
    const size_t i1 = (size_t)(b * T_ + row1) * C_ + h * D_;
#pragma unroll
    for (int nf = 0; nf < 8; ++nf) {
        const int d = nf * 8 + tc;
        __nv_bfloat16 h0, l0, h1, l1;
        split2(o[nf][0] * inv0, h0, l0); split2(o[nf][1] * inv0, h1, l1);
        *(uint32_t*)&g_attH[i0 + d] = pack2(h0, h1);
        *(uint32_t*)&g_attL[i0 + d] = pack2(l0, l1);
        split2(o[nf][2] * inv1, h0, l0); split2(o[nf][3] * inv1, h1, l1);
        *(uint32_t*)&g_attH[i1 + d] = pack2(h0, h1);
        *(uint32_t*)&g_attL[i1 + d] = pack2(l0, l1);
    }
}

// ---------------------------------------------------------------------------
extern "C" void kernel_launch(void* const* d_in, const int* in_sizes, int n_in,
                              void* d_out, int out_size)
{
    const float* x      = (const float*)d_in[0];
    const float* w_qkv  = (const float*)d_in[1];
    const float* b_qkv  = (const float*)d_in[2];
    const float* w_proj = (const float*)d_in[3];
    const float* b_proj = (const float*)d_in[4];
    float* out = (float*)d_out;

    cudaFuncSetAttribute(gemm_mma<0>, cudaFuncAttributeMaxDynamicSharedMemorySize, SMEM_G);
    cudaFuncSetAttribute(gemm_mma<1>, cudaFuncAttributeMaxDynamicSharedMemorySize, SMEM_G);

    // 0) pre-split inputs to bf16 hi/lo
    {
        int n4x = (B_ * T_ * C_) / 4;
        int n4q = (C_ * 3 * C_) / 4;
        int n4p = (C_ * C_) / 4;
        split_kernel<0><<<(n4x + 255) / 256, 256>>>(x, n4x);
        split_kernel<1><<<(n4q + 255) / 256, 256>>>(w_qkv, n4q);
        split_kernel<2><<<(n4p + 255) / 256, 256>>>(w_proj, n4p);
    }

    // 1) QKV projection (HMMA bf16x3, cp.async pipelined)
    gemm_mma<0><<<dim3((3 * C_) / 128, (B_ * T_) / 128), 256, SMEM_G>>>(
        b_qkv, nullptr, B_ * T_, 3 * C_, C_);

    // 2) causal flash attention (HMMA bf16x3) -> g_att hi/lo
    attn_mma<<<dim3(T_ / 128, B_ * H_), 256>>>();

    // 3) output projection (HMMA bf16x3, cp.async pipelined)
    gemm_mma<1><<<dim3(C_ / 128, (B_ * T_) / 128), 256, SMEM_G>>>(
        b_proj, out, B_ * T_, C_, C_);
}